// round 11
// baseline (speedup 1.0000x reference)
#include <cuda_runtime.h>
#include <stdint.h>

#define NB   256
#define NK   64
#define NL   32
#define NM   (NK * NL)            // 2048 rows per (side, batch) block
#define NTOT (2 * NB * NM)        // 1,048,576 output rows
#define SENT 32
#define TBL  4096
#define TMASK 4095u
#define EMPTYV 0xFFFFFFFFu
#define NODE_MASK 0x1FFFFu        // node ids < 100000 < 2^17
#define VALIDF 0x80000000u

#define CTAS 592                  // 4 * 148 SMs: one co-resident wave
#define RPC  1772                 // ceil(NTOT / CTAS); slice spans <= 2 blocks
#define NTABS 512                 // one builder CTA per (side, batch) table

#define BAR_AUX    1              // 128-thread aux barrier
#define BAR_HANDOF 3              // prepass handoff: 384 arrive + 128 sync
#define BAR_STREAM 4              // 384-thread stream barrier

// first-seen tables (8 MB, L2-resident)
__device__ uint32_t g_tab[NTABS * TBL];
// monotonic per-CTA epoch slots: +1 per slot per run -> replay-safe
__device__ unsigned g_ready[CTAS];

__device__ __forceinline__ int ht_lookup_g(const uint32_t* __restrict__ tab, uint32_t node) {
    uint32_t h = (node * 2654435761u) & TMASK;
    #pragma unroll 1
    for (;;) {
        uint32_t cur = __ldg(&tab[h]);
        if (cur == EMPTYV) return SENT;
        if ((cur & NODE_MASK) == node) return (int)(cur >> 17);
        h = (h + 1) & TMASK;
    }
}

__global__ __launch_bounds__(512, 4) void wpe_kernel(
    const int* __restrict__ src_walks, const int* __restrict__ tgt_walks,
    const int* __restrict__ src_lens,  const int* __restrict__ tgt_lens,
    const float* __restrict__ own_emb, const float* __restrict__ cross_emb,
    float* __restrict__ out)
{
    __shared__ uint32_t tab[TBL];         // 16 KB (builder aux warps only)
    __shared__ uint32_t s_info[RPC + 4];  // 7 KB: node|valid -> code|valid

    const int bid = blockIdx.x;
    const int tid = threadIdx.x;
    const int warp = tid >> 5, lane = tid & 31;
    const int half = lane >> 4, col = lane & 15;

    long r0 = (long)bid * RPC;
    long r1 = r0 + RPC; if (r1 > NTOT) r1 = NTOT;
    const int cnt = (int)(r1 - r0);

    float4* out4 = (float4*)out;

    if (warp < 4) {
        // ════════ AUX group (128 threads): build → publish → wait → resolve ════════
        unsigned E = 0;
        if (bid < NTABS) {
            const int s = bid >> 8, b = bid & (NB - 1);
            const int* w  = (s == 0 ? src_walks : tgt_walks) + b * NM;
            const int* ln = (s == 0 ? src_lens  : tgt_lens)  + b * NK;

            for (int i = tid; i < TBL; i += 128) tab[i] = EMPTYV;
            asm volatile("bar.sync %0, %1;" :: "r"(BAR_AUX), "r"(128) : "memory");

            #pragma unroll
            for (int r = 0; r < NM / 128; r++) {
                int m = tid + r * 128;
                int node = w[m];
                int l = m & (NL - 1);
                if (node != 0 && l < ln[m >> 5]) {
                    uint32_t packed = ((uint32_t)l << 17) | (uint32_t)node;
                    uint32_t h = ((uint32_t)node * 2654435761u) & TMASK;
                    #pragma unroll 1
                    for (;;) {
                        uint32_t cur = tab[h];
                        if (cur == EMPTYV) {
                            cur = atomicCAS(&tab[h], EMPTYV, packed);
                            if (cur == EMPTYV) break;
                        }
                        if ((cur & NODE_MASK) == (uint32_t)node) {
                            atomicMin(&tab[h], packed);   // same key: packed-min == pos-min
                            break;
                        }
                        h = (h + 1) & TMASK;
                    }
                }
            }
            asm volatile("bar.sync %0, %1;" :: "r"(BAR_AUX), "r"(128) : "memory");

            uint4* dst = (uint4*)(g_tab + (size_t)bid * TBL);
            const uint4* srcv = (const uint4*)tab;
            #pragma unroll
            for (int i = tid; i < TBL / 4; i += 128) dst[i] = srcv[i];
            asm volatile("bar.sync %0, %1;" :: "r"(BAR_AUX), "r"(128) : "memory");
        }

        __shared__ unsigned sh_E;
        if (tid == 0) {
            if (bid < NTABS) __threadfence();               // publish table dump
            sh_E = atomicAdd(&g_ready[bid], 1u) + 1u;       // learn run epoch
        }

        // wait for prepass handoff from stream group
        asm volatile("bar.sync %0, %1;" :: "r"(BAR_HANDOF), "r"(512) : "memory");
        E = sh_E;

        // wait for the <=2 batches' tables (zero-emit gives huge slack)
        if (tid == 0) {
            const int b0 = (int)((r0 >> 11) & (NB - 1));
            const int b1 = (int)(((r1 - 1) >> 11) & (NB - 1));
            while (*(volatile unsigned*)&g_ready[b0]       < E) __nanosleep(32);
            while (*(volatile unsigned*)&g_ready[256 + b0] < E) __nanosleep(32);
            if (b1 != b0) {
                while (*(volatile unsigned*)&g_ready[b1]       < E) __nanosleep(32);
                while (*(volatile unsigned*)&g_ready[256 + b1] < E) __nanosleep(32);
            }
            __threadfence();                                // acquire tables
        }
        asm volatile("bar.sync %0, %1;" :: "r"(BAR_AUX), "r"(128) : "memory");

        // resolve all valid rows (runs concurrently with stream zero-emit)
        for (int i = tid; i < cnt; i += 128) {
            uint32_t info = s_info[i];
            if (info & VALIDF) {
                long r = r0 + i;
                const int s = (int)(r >> 19);
                const int b = (int)((r >> 11) & (NB - 1));
                uint32_t node = info & NODE_MASK;
                const uint32_t* mytab = g_tab + ((size_t)(s       * NB + b)) * TBL;
                const uint32_t* xtab  = g_tab + ((size_t)((s ^ 1) * NB + b)) * TBL;
                int own   = ht_lookup_g(mytab, node);
                int cross = ht_lookup_g(xtab,  node);
                s_info[i] = (uint32_t)(own | (cross << 6)) | VALIDF;
            }
        }
    } else {
        // ════════ STREAM group (384 threads): prepass → zero-emit ════════
        const int st = tid - 128;
        for (int i = st; i < cnt; i += 384) {
            long r = r0 + i;
            const int s = (int)(r >> 19);
            const int b = (int)((r >> 11) & (NB - 1));
            const int m = (int)(r & (NM - 1));
            const int* w  = (s == 0 ? src_walks : tgt_walks) + b * NM;
            const int* ln = (s == 0 ? src_lens  : tgt_lens)  + b * NK;
            int node = w[m];
            int l = m & (NL - 1);
            s_info[i] = (node != 0 && l < ln[m >> 5]) ? ((uint32_t)node | VALIDF) : 0u;
        }
        asm volatile("bar.arrive %0, %1;" :: "r"(BAR_HANDOF), "r"(512) : "memory");
        asm volatile("bar.sync %0, %1;"   :: "r"(BAR_STREAM), "r"(384) : "memory");

        // emit zeros for invalid rows: stores start immediately, no deps
        const float4 z4 = make_float4(0.f, 0.f, 0.f, 0.f);
        const int ws = warp - 4;                    // 0..11
        for (int i = ws; i < cnt; i += 12)
            if (!(s_info[i] & VALIDF))
                __stcs(&out4[(size_t)(r0 + i) * 32 + lane], z4);
    }

    __syncthreads();    // converged join: resolve done, zero-emit done

    // ════════ all 16 warps: emit valid rows ════════
    const float4* oe = (const float4*)own_emb;     // 33 rows x 16 float4
    const float4* ce = (const float4*)cross_emb;

    int i = warp;
    for (; i + 64 <= cnt; i += 64) {               // 4-deep batches for store MLP
        uint32_t p[4];
        #pragma unroll
        for (int j = 0; j < 4; j++) p[j] = s_info[i + j * 16];
        #pragma unroll
        for (int j = 0; j < 4; j++) {
            if (p[j] & VALIDF) {
                int own   = p[j] & 63;
                int cross = (p[j] >> 6) & 63;
                float4 v = half ? __ldg(&ce[cross * 16 + col])
                                : __ldg(&oe[own   * 16 + col]);
                __stcs(&out4[(size_t)(r0 + i + j * 16) * 32 + lane], v);
            }
        }
    }
    for (; i < cnt; i += 16) {                     // remainder
        uint32_t p = s_info[i];
        if (p & VALIDF) {
            int own   = p & 63;
            int cross = (p >> 6) & 63;
            float4 v = half ? __ldg(&ce[cross * 16 + col])
                            : __ldg(&oe[own   * 16 + col]);
            __stcs(&out4[(size_t)(r0 + i) * 32 + lane], v);
        }
    }
}

extern "C" void kernel_launch(void* const* d_in, const int* in_sizes, int n_in,
                              void* d_out, int out_size) {
    (void)in_sizes; (void)n_in; (void)out_size;
    wpe_kernel<<<CTAS, 512>>>(
        (const int*)d_in[0], (const int*)d_in[1],
        (const int*)d_in[2], (const int*)d_in[3],
        (const float*)d_in[4], (const float*)d_in[5],
        (float*)d_out);
}

// round 12
// speedup vs baseline: 1.1518x; 1.1518x over previous
#include <cuda_runtime.h>
#include <stdint.h>

#define NB   256
#define NK   64
#define NL   32
#define NM   (NK * NL)            // 2048 rows per (side, batch) block
#define NTOT (2 * NB * NM)        // 1,048,576 output rows
#define SENT 32
#define TBL  4096
#define TMASK 4095u
#define EMPTYV 0xFFFFFFFFu
#define NODE_MASK 0x1FFFFu        // node ids < 100000 < 2^17
#define VALIDF 0x80000000u

#define CTAS 592                  // 4 * 148 SMs: one co-resident wave
#define RPC  1772                 // ceil(NTOT / CTAS); slice spans <= 2 blocks
#define NTABS 512                 // one builder CTA per (side, batch) table

// first-seen tables (8 MB, L2-resident)
__device__ uint32_t g_tab[NTABS * TBL];
// monotonic per-CTA epoch slots: +1 per slot per run -> replay-safe
__device__ unsigned g_ready[CTAS];

__device__ __forceinline__ int ht_lookup_g(const uint32_t* __restrict__ tab, uint32_t node) {
    uint32_t h = (node * 2654435761u) & TMASK;
    #pragma unroll 1
    for (;;) {
        uint32_t cur = __ldg(&tab[h]);
        if (cur == EMPTYV) return SENT;
        if ((cur & NODE_MASK) == node) return (int)(cur >> 17);
        h = (h + 1) & TMASK;
    }
}

__global__ __launch_bounds__(512, 4) void wpe_kernel(
    const int* __restrict__ src_walks, const int* __restrict__ tgt_walks,
    const int* __restrict__ src_lens,  const int* __restrict__ tgt_lens,
    const float* __restrict__ own_emb, const float* __restrict__ cross_emb,
    float* __restrict__ out)
{
    __shared__ uint32_t tab[TBL];         // 16 KB (builders only)
    __shared__ uint32_t s_info[RPC + 4];  // 7 KB: node|valid -> code|valid

    const int bid = blockIdx.x;
    const int tid = threadIdx.x;
    const int warp = tid >> 5, lane = tid & 31;
    const int half = lane >> 4, col = lane & 15;

    long r0 = (long)bid * RPC;
    long r1 = r0 + RPC; if (r1 > NTOT) r1 = NTOT;
    const int cnt = (int)(r1 - r0);

    __shared__ unsigned sh_E;

    // helper lambda-free prepass body is inlined twice below (different strides)

    // ── stage 1: builders make ONE (side,batch) table ──
    if (bid < NTABS) {
        const int s = bid >> 8, b = bid & (NB - 1);
        const int* w  = (s == 0 ? src_walks : tgt_walks) + b * NM;
        const int* ln = (s == 0 ? src_lens  : tgt_lens)  + b * NK;

        for (int i = tid; i < TBL; i += 512) tab[i] = EMPTYV;
        __syncthreads();

        #pragma unroll
        for (int r = 0; r < NM / 512; r++) {
            int m = tid + r * 512;
            int node = w[m];
            int l = m & (NL - 1);
            if (node != 0 && l < ln[m >> 5]) {
                uint32_t packed = ((uint32_t)l << 17) | (uint32_t)node;
                uint32_t h = ((uint32_t)node * 2654435761u) & TMASK;
                #pragma unroll 1
                for (;;) {
                    uint32_t cur = tab[h];
                    if (cur == EMPTYV) {
                        cur = atomicCAS(&tab[h], EMPTYV, packed);
                        if (cur == EMPTYV) break;
                    }
                    if ((cur & NODE_MASK) == (uint32_t)node) {
                        atomicMin(&tab[h], packed);   // same key: packed-min == pos-min
                        break;
                    }
                    h = (h + 1) & TMASK;
                }
            }
        }
        __syncthreads();

        // ── stage 1b: OVERLAP — warps 0..7 dump table, warps 8..15 do prepass ──
        if (warp < 8) {
            uint4* dst = (uint4*)(g_tab + (size_t)bid * TBL);
            const uint4* srcv = (const uint4*)tab;
            #pragma unroll
            for (int i = tid; i < TBL / 4; i += 256) dst[i] = srcv[i];
        } else {
            const int st = tid - 256;
            for (int i = st; i < cnt; i += 256) {
                long r = r0 + i;
                const int ss = (int)(r >> 19);
                const int bb = (int)((r >> 11) & (NB - 1));
                const int m  = (int)(r & (NM - 1));
                const int* ww  = (ss == 0 ? src_walks : tgt_walks) + bb * NM;
                const int* lln = (ss == 0 ? src_lens  : tgt_lens)  + bb * NK;
                int node = ww[m];
                int l = m & (NL - 1);
                s_info[i] = (node != 0 && l < lln[m >> 5]) ? ((uint32_t)node | VALIDF) : 0u;
            }
        }
        __syncthreads();
        if (tid == 0) {
            __threadfence();                               // publish table dump
            sh_E = atomicAdd(&g_ready[bid], 1u) + 1u;      // learn run epoch
        }
    } else {
        // non-builder: prepass with all 512 threads
        for (int i = tid; i < cnt; i += 512) {
            long r = r0 + i;
            const int ss = (int)(r >> 19);
            const int bb = (int)((r >> 11) & (NB - 1));
            const int m  = (int)(r & (NM - 1));
            const int* ww  = (ss == 0 ? src_walks : tgt_walks) + bb * NM;
            const int* lln = (ss == 0 ? src_lens  : tgt_lens)  + bb * NK;
            int node = ww[m];
            int l = m & (NL - 1);
            s_info[i] = (node != 0 && l < lln[m >> 5]) ? ((uint32_t)node | VALIDF) : 0u;
        }
        if (tid == 0) sh_E = atomicAdd(&g_ready[bid], 1u) + 1u;
    }
    __syncthreads();
    const unsigned E = sh_E;

    // ── stage 3: emit zeros for invalid rows NOW (overlaps builder latency) ──
    float4* out4 = (float4*)out;
    const float4 z4 = make_float4(0.f, 0.f, 0.f, 0.f);
    {
        int i = warp;
        for (; i + 64 <= cnt; i += 64) {           // 4-deep batches for store MLP
            uint32_t p[4];
            #pragma unroll
            for (int j = 0; j < 4; j++) p[j] = s_info[i + j * 16];
            #pragma unroll
            for (int j = 0; j < 4; j++)
                if (!(p[j] & VALIDF))
                    __stcs(&out4[(size_t)(r0 + i + j * 16) * 32 + lane], z4);
        }
        for (; i < cnt; i += 16)
            if (!(s_info[i] & VALIDF))
                __stcs(&out4[(size_t)(r0 + i) * 32 + lane], z4);
    }

    // ── stage 4: wait for the <=2 batches' tables (usually already done) ──
    if (tid == 0) {
        const int b0 = (int)((r0 >> 11) & (NB - 1));
        const int b1 = (int)(((r1 - 1) >> 11) & (NB - 1));
        while (*(volatile unsigned*)&g_ready[b0]       < E) __nanosleep(32);
        while (*(volatile unsigned*)&g_ready[256 + b0] < E) __nanosleep(32);
        if (b1 != b0) {
            while (*(volatile unsigned*)&g_ready[b1]       < E) __nanosleep(32);
            while (*(volatile unsigned*)&g_ready[256 + b1] < E) __nanosleep(32);
        }
        __threadfence();                                   // acquire tables
    }
    __syncthreads();

    // ── stage 5: resolve valid rows from L2 tables ──
    for (int i = tid; i < cnt; i += 512) {
        uint32_t info = s_info[i];
        if (info & VALIDF) {
            long r = r0 + i;
            const int s = (int)(r >> 19);
            const int b = (int)((r >> 11) & (NB - 1));
            uint32_t node = info & NODE_MASK;
            const uint32_t* mytab = g_tab + ((size_t)(s       * NB + b)) * TBL;
            const uint32_t* xtab  = g_tab + ((size_t)((s ^ 1) * NB + b)) * TBL;
            int own   = ht_lookup_g(mytab, node);
            int cross = ht_lookup_g(xtab,  node);
            s_info[i] = (uint32_t)(own | (cross << 6)) | VALIDF;
        }
    }
    __syncthreads();

    // ── stage 6: emit valid rows (4-deep batching for store MLP) ──
    const float4* oe = (const float4*)own_emb;     // 33 rows x 16 float4
    const float4* ce = (const float4*)cross_emb;

    int i = warp;
    for (; i + 64 <= cnt; i += 64) {
        uint32_t p[4];
        #pragma unroll
        for (int j = 0; j < 4; j++) p[j] = s_info[i + j * 16];
        #pragma unroll
        for (int j = 0; j < 4; j++) {
            if (p[j] & VALIDF) {
                int own   = p[j] & 63;
                int cross = (p[j] >> 6) & 63;
                float4 v = half ? __ldg(&ce[cross * 16 + col])
                                : __ldg(&oe[own   * 16 + col]);
                __stcs(&out4[(size_t)(r0 + i + j * 16) * 32 + lane], v);
            }
        }
    }
    for (; i < cnt; i += 16) {
        uint32_t p = s_info[i];
        if (p & VALIDF) {
            int own   = p & 63;
            int cross = (p >> 6) & 63;
            float4 v = half ? __ldg(&ce[cross * 16 + col])
                            : __ldg(&oe[own   * 16 + col]);
            __stcs(&out4[(size_t)(r0 + i) * 32 + lane], v);
        }
    }
}

extern "C" void kernel_launch(void* const* d_in, const int* in_sizes, int n_in,
                              void* d_out, int out_size) {
    (void)in_sizes; (void)n_in; (void)out_size;
    wpe_kernel<<<CTAS, 512>>>(
        (const int*)d_in[0], (const int*)d_in[1],
        (const int*)d_in[2], (const int*)d_in[3],
        (const float*)d_in[4], (const float*)d_in[5],
        (float*)d_out);
}